// round 1
// baseline (speedup 1.0000x reference)
#include <cuda_runtime.h>

#define NN 1024
#define FF 128
#define LOG2E 1.4426950408889634f

// Scratch (allocation-free rule: __device__ globals)
__device__ float g_A2[NN * FF];       // -log2e * (input @ w1a^T)          [j,f]
__device__ float g_B2[NN * FF];       // -log2e * (input @ w1b^T + b1)     [i,f]
__device__ float g_P [NN * FF];       // input @ weight                    [j,g]
__device__ float g_S [NN * NN];       // adj * sum_f sigmoid(...)          [i,j]

__device__ __forceinline__ float ex2f(float x) {
    float y; asm("ex2.approx.f32 %0, %1;" : "=f"(y) : "f"(x)); return y;
}
__device__ __forceinline__ float rcpf(float x) {
    float y; asm("rcp.approx.f32 %0, %1;" : "=f"(y) : "f"(x)); return y;
}

// ---------------------------------------------------------------------------
// Kernel 1: A2, B2, P  — three small [1024,128] GEMMs with K=128.
// grid (64, 3), block 128 (thread = output column f/g). 16 rows per block.
// ---------------------------------------------------------------------------
__global__ void prep_kernel(const float* __restrict__ input,
                            const float* __restrict__ w1,
                            const float* __restrict__ b1,
                            const float* __restrict__ weight)
{
    const int mat = blockIdx.y;       // 0 = A2, 1 = B2, 2 = P
    const int j0  = blockIdx.x * 16;
    const int t   = threadIdx.x;      // 0..127

    __shared__ float in_s[16][FF];
    #pragma unroll
    for (int r = 0; r < 16; r++) in_s[r][t] = input[(j0 + r) * FF + t];
    __syncthreads();

    float acc[16];
    #pragma unroll
    for (int r = 0; r < 16; r++) acc[r] = 0.f;

    if (mat < 2) {
        // C[j,f] = sum_k input[j,k] * w1[f, (mat?128:0)+k]
        const float4* wrow = (const float4*)(w1 + t * 256 + (mat ? 128 : 0));
        #pragma unroll 4
        for (int k4 = 0; k4 < 32; k4++) {
            float4 w = wrow[k4];
            int k = k4 * 4;
            #pragma unroll
            for (int r = 0; r < 16; r++) {
                acc[r] += in_s[r][k + 0] * w.x;
                acc[r] += in_s[r][k + 1] * w.y;
                acc[r] += in_s[r][k + 2] * w.z;
                acc[r] += in_s[r][k + 3] * w.w;
            }
        }
        if (mat == 0) {
            #pragma unroll
            for (int r = 0; r < 16; r++)
                g_A2[(j0 + r) * FF + t] = -LOG2E * acc[r];
        } else {
            float bb = b1[t];
            #pragma unroll
            for (int r = 0; r < 16; r++)
                g_B2[(j0 + r) * FF + t] = -LOG2E * (acc[r] + bb);
        }
    } else {
        // P[j,g] = sum_k input[j,k] * weight[k,g]
        #pragma unroll 4
        for (int k = 0; k < 128; k++) {
            float wv = weight[k * FF + t];
            #pragma unroll
            for (int r = 0; r < 16; r++) acc[r] += in_s[r][k] * wv;
        }
        #pragma unroll
        for (int r = 0; r < 16; r++)
            g_P[(j0 + r) * FF + t] = acc[r];
    }
}

// ---------------------------------------------------------------------------
// Kernel 2 (dominant): S[i,j] = adj[i,j] * sum_f 1/(1 + 2^(A2[j,f]+B2[i,f]))
// grid (32, 32), block 256. 32x32 tile of (i,j); thread owns 2x2 at stride 16.
// Per element: FADD -> EX2 -> FADD -> RCP -> FADD (MUFU-bound).
// ---------------------------------------------------------------------------
__global__ void gate_kernel(const float* __restrict__ adj)
{
    __shared__ float a_s[32][132];   // A2 rows for j-tile (pad: stride 132)
    __shared__ float b_s[32][132];   // B2 rows for i-tile

    const int t  = threadIdx.x;              // 0..255
    const int i0 = blockIdx.y * 32;
    const int j0 = blockIdx.x * 32;

    for (int idx = t; idx < 32 * FF; idx += 256) {
        int r = idx >> 7, c = idx & 127;
        a_s[r][c] = g_A2[(j0 + r) * FF + c];
        b_s[r][c] = g_B2[(i0 + r) * FF + c];
    }
    __syncthreads();

    const int ti = t >> 4;       // 0..15 -> i rows {ti, ti+16}
    const int tj = t & 15;       // 0..15 -> j rows {tj, tj+16}

    float acc00 = 0.f, acc01 = 0.f, acc10 = 0.f, acc11 = 0.f;

#define TERM(av, bv) rcpf(1.0f + ex2f((av) + (bv)))

    #pragma unroll 2
    for (int f = 0; f < FF; f += 4) {
        float4 aA = *(const float4*)&a_s[tj     ][f];
        float4 aB = *(const float4*)&a_s[tj + 16][f];
        float4 bA = *(const float4*)&b_s[ti     ][f];
        float4 bB = *(const float4*)&b_s[ti + 16][f];

        acc00 += TERM(aA.x, bA.x); acc00 += TERM(aA.y, bA.y);
        acc00 += TERM(aA.z, bA.z); acc00 += TERM(aA.w, bA.w);

        acc01 += TERM(aB.x, bA.x); acc01 += TERM(aB.y, bA.y);
        acc01 += TERM(aB.z, bA.z); acc01 += TERM(aB.w, bA.w);

        acc10 += TERM(aA.x, bB.x); acc10 += TERM(aA.y, bB.y);
        acc10 += TERM(aA.z, bB.z); acc10 += TERM(aA.w, bB.w);

        acc11 += TERM(aB.x, bB.x); acc11 += TERM(aB.y, bB.y);
        acc11 += TERM(aB.z, bB.z); acc11 += TERM(aB.w, bB.w);
    }
#undef TERM

    const int ia = i0 + ti, ib = i0 + ti + 16;
    const int ja = j0 + tj, jb = j0 + tj + 16;
    g_S[ia * NN + ja] = adj[ia * NN + ja] * acc00;
    g_S[ia * NN + jb] = adj[ia * NN + jb] * acc01;
    g_S[ib * NN + ja] = adj[ib * NN + ja] * acc10;
    g_S[ib * NN + jb] = adj[ib * NN + jb] * acc11;
}

// ---------------------------------------------------------------------------
// Kernel 3: out[i,g] = sum_j S[i,j] * P[j,g] + bias[g]
// grid 128, block 256. 8 i-rows per block; thread = (g, i-group of 4).
// ---------------------------------------------------------------------------
__global__ void out_kernel(const float* __restrict__ bias,
                           float* __restrict__ out)
{
    const int t  = threadIdx.x;         // 0..255
    const int g  = t & 127;
    const int ig = t >> 7;              // 0..1 -> rows ig*4 .. ig*4+3
    const int i0 = blockIdx.x * 8;

    __shared__ float S_s[8][64];

    float acc0 = 0.f, acc1 = 0.f, acc2 = 0.f, acc3 = 0.f;
    const int rb = ig * 4;

    for (int jt = 0; jt < NN; jt += 64) {
        __syncthreads();
        for (int idx = t; idx < 8 * 64; idx += 256) {
            int r = idx >> 6, c = idx & 63;
            S_s[r][c] = g_S[(i0 + r) * NN + jt + c];
        }
        __syncthreads();

        #pragma unroll 4
        for (int jj = 0; jj < 64; jj += 4) {
            float4 s0 = *(const float4*)&S_s[rb + 0][jj];
            float4 s1 = *(const float4*)&S_s[rb + 1][jj];
            float4 s2 = *(const float4*)&S_s[rb + 2][jj];
            float4 s3 = *(const float4*)&S_s[rb + 3][jj];
            float p0 = g_P[(jt + jj + 0) * FF + g];
            float p1 = g_P[(jt + jj + 1) * FF + g];
            float p2 = g_P[(jt + jj + 2) * FF + g];
            float p3 = g_P[(jt + jj + 3) * FF + g];
            acc0 += s0.x * p0; acc0 += s0.y * p1; acc0 += s0.z * p2; acc0 += s0.w * p3;
            acc1 += s1.x * p0; acc1 += s1.y * p1; acc1 += s1.z * p2; acc1 += s1.w * p3;
            acc2 += s2.x * p0; acc2 += s2.y * p1; acc2 += s2.z * p2; acc2 += s2.w * p3;
            acc3 += s3.x * p0; acc3 += s3.y * p1; acc3 += s3.z * p2; acc3 += s3.w * p3;
        }
    }

    const float bv = bias[g];
    out[(i0 + rb + 0) * FF + g] = acc0 + bv;
    out[(i0 + rb + 1) * FF + g] = acc1 + bv;
    out[(i0 + rb + 2) * FF + g] = acc2 + bv;
    out[(i0 + rb + 3) * FF + g] = acc3 + bv;
}

// ---------------------------------------------------------------------------
extern "C" void kernel_launch(void* const* d_in, const int* in_sizes, int n_in,
                              void* d_out, int out_size)
{
    const float* input   = (const float*)d_in[0];   // [1024,128]
    const float* adj     = (const float*)d_in[1];   // [1024,1024]
    // d_in[2] = feat_adj : unused by the reference
    const float* weight  = (const float*)d_in[3];   // [128,128]
    const float* bias    = (const float*)d_in[4];   // [128]
    const float* w1      = (const float*)d_in[5];   // [128,256]
    const float* b1      = (const float*)d_in[6];   // [128]
    float* out = (float*)d_out;                     // [1024,128]

    prep_kernel<<<dim3(64, 3), 128>>>(input, w1, b1, weight);
    gate_kernel<<<dim3(32, 32), 256>>>(adj);
    out_kernel<<<128, 256>>>(bias, out);
}

// round 2
// speedup vs baseline: 1.6402x; 1.6402x over previous
#include <cuda_runtime.h>

#define NN 1024
#define FF 128

// Scratch (allocation-free rule: __device__ globals)
__device__ float g_A2[NN * FF];       // 0.5 * (input @ w1a^T)             [j,f]
__device__ float g_B2[NN * FF];       // 0.5 * (input @ w1b^T + b1)        [i,f]
__device__ float g_P [NN * FF];       // input @ weight                    [j,g]
__device__ float g_S [NN * NN];       // adj * sum_f sigmoid(...)          [i,j]

__device__ __forceinline__ float tanhf_approx(float x) {
    float y; asm("tanh.approx.f32 %0, %1;" : "=f"(y) : "f"(x)); return y;
}

// ---------------------------------------------------------------------------
// Kernel 1: A2, B2, P  — three [1024,128] GEMMs with K=128.
// grid (64, 3), block 128. Thread = output column. w1 staged via smem
// (coalesced) in K-chunks of 32 to fix the round-1 uncoalesced-stride-1KB bug.
// ---------------------------------------------------------------------------
__global__ void prep_kernel(const float* __restrict__ input,
                            const float* __restrict__ w1,
                            const float* __restrict__ b1,
                            const float* __restrict__ weight)
{
    const int mat = blockIdx.y;       // 0 = A2, 1 = B2, 2 = P
    const int j0  = blockIdx.x * 16;
    const int t   = threadIdx.x;      // 0..127

    __shared__ float in_s[16][FF];
    __shared__ float w_s[128][33];    // pad 33: conflict-free w_s[t][k] reads

    #pragma unroll
    for (int r = 0; r < 16; r++) in_s[r][t] = input[(j0 + r) * FF + t];

    float acc[16];
    #pragma unroll
    for (int r = 0; r < 16; r++) acc[r] = 0.f;

    if (mat < 2) {
        const int off = mat ? 128 : 0;
        for (int k0 = 0; k0 < 128; k0 += 32) {
            __syncthreads();
            // coalesced w1 load: 4096 elems, warp covers 32 consecutive k
            #pragma unroll
            for (int idx = t; idx < 128 * 32; idx += 128) {
                int f = idx >> 5, k = idx & 31;
                w_s[f][k] = w1[f * 256 + off + k0 + k];
            }
            __syncthreads();
            #pragma unroll
            for (int k4 = 0; k4 < 8; k4++) {
                int k = k4 * 4;
                float w0 = w_s[t][k + 0];
                float w1v = w_s[t][k + 1];
                float w2 = w_s[t][k + 2];
                float w3 = w_s[t][k + 3];
                #pragma unroll
                for (int r = 0; r < 16; r++) {
                    float4 iv = *(const float4*)&in_s[r][k0 + k];
                    acc[r] += iv.x * w0;
                    acc[r] += iv.y * w1v;
                    acc[r] += iv.z * w2;
                    acc[r] += iv.w * w3;
                }
            }
        }
        if (mat == 0) {
            #pragma unroll
            for (int r = 0; r < 16; r++)
                g_A2[(j0 + r) * FF + t] = 0.5f * acc[r];
        } else {
            float bb = b1[t];
            #pragma unroll
            for (int r = 0; r < 16; r++)
                g_B2[(j0 + r) * FF + t] = 0.5f * (acc[r] + bb);
        }
    } else {
        __syncthreads();
        // P[j,g] = sum_k input[j,k] * weight[k,g] ; weight reads coalesced
        #pragma unroll 4
        for (int k = 0; k < 128; k++) {
            float wv = weight[k * FF + t];
            #pragma unroll
            for (int r = 0; r < 16; r++) acc[r] += in_s[r][k] * wv;
        }
        #pragma unroll
        for (int r = 0; r < 16; r++)
            g_P[(j0 + r) * FF + t] = acc[r];
    }
}

// ---------------------------------------------------------------------------
// Kernel 2 (dominant): S[i,j] = adj[i,j] * (64 + 0.5 * sum_f tanh(A2+B2))
// sigmoid(x) = 0.5 + 0.5*tanh(x/2)  -> one MUFU per element instead of two.
// grid (32, 32), block 256. 32x32 tile of (i,j); thread owns 2x2 at stride 16.
// ---------------------------------------------------------------------------
__global__ void gate_kernel(const float* __restrict__ adj)
{
    __shared__ float a_s[32][132];   // A2 rows for j-tile (pad: stride 132)
    __shared__ float b_s[32][132];   // B2 rows for i-tile

    const int t  = threadIdx.x;              // 0..255
    const int i0 = blockIdx.y * 32;
    const int j0 = blockIdx.x * 32;

    for (int idx = t; idx < 32 * FF; idx += 256) {
        int r = idx >> 7, c = idx & 127;
        a_s[r][c] = g_A2[(j0 + r) * FF + c];
        b_s[r][c] = g_B2[(i0 + r) * FF + c];
    }
    __syncthreads();

    const int ti = t >> 4;       // 0..15 -> i rows {ti, ti+16}
    const int tj = t & 15;       // 0..15 -> j rows {tj, tj+16}

    float acc00 = 0.f, acc01 = 0.f, acc10 = 0.f, acc11 = 0.f;

#define TERM(av, bv) tanhf_approx((av) + (bv))

    #pragma unroll 2
    for (int f = 0; f < FF; f += 4) {
        float4 aA = *(const float4*)&a_s[tj     ][f];
        float4 aB = *(const float4*)&a_s[tj + 16][f];
        float4 bA = *(const float4*)&b_s[ti     ][f];
        float4 bB = *(const float4*)&b_s[ti + 16][f];

        acc00 += TERM(aA.x, bA.x); acc00 += TERM(aA.y, bA.y);
        acc00 += TERM(aA.z, bA.z); acc00 += TERM(aA.w, bA.w);

        acc01 += TERM(aB.x, bA.x); acc01 += TERM(aB.y, bA.y);
        acc01 += TERM(aB.z, bA.z); acc01 += TERM(aB.w, bA.w);

        acc10 += TERM(aA.x, bB.x); acc10 += TERM(aA.y, bB.y);
        acc10 += TERM(aA.z, bB.z); acc10 += TERM(aA.w, bB.w);

        acc11 += TERM(aB.x, bB.x); acc11 += TERM(aB.y, bB.y);
        acc11 += TERM(aB.z, bB.z); acc11 += TERM(aB.w, bB.w);
    }
#undef TERM

    const int ia = i0 + ti, ib = i0 + ti + 16;
    const int ja = j0 + tj, jb = j0 + tj + 16;
    g_S[ia * NN + ja] = adj[ia * NN + ja] * (64.0f + 0.5f * acc00);
    g_S[ia * NN + jb] = adj[ia * NN + jb] * (64.0f + 0.5f * acc01);
    g_S[ib * NN + ja] = adj[ib * NN + ja] * (64.0f + 0.5f * acc10);
    g_S[ib * NN + jb] = adj[ib * NN + jb] * (64.0f + 0.5f * acc11);
}

// ---------------------------------------------------------------------------
// Kernel 3: out[i,g] = sum_j S[i,j] * P[j,g] + bias[g]
// grid 128, block 256. Tile: 8 i-rows x 128 g. K chunk 64 j, both operands
// staged in smem. Thread = (ti = i row, tg -> 4 g columns), float4 micro-tile.
// ---------------------------------------------------------------------------
__global__ void out_kernel(const float* __restrict__ bias,
                           float* __restrict__ out)
{
    const int t  = threadIdx.x;         // 0..255
    const int ti = t >> 5;              // 0..7  : i row
    const int tg = (t & 31) * 4;        // g base: 0..124 step 4
    const int i0 = blockIdx.x * 8;

    __shared__ float P_s[64][FF];       // 32 KB
    __shared__ float S_s[8][64];        // 2 KB

    float acc0 = 0.f, acc1 = 0.f, acc2 = 0.f, acc3 = 0.f;

    for (int jt = 0; jt < NN; jt += 64) {
        __syncthreads();
        // P tile: 8192 elems, float4-coalesced
        #pragma unroll
        for (int idx = t * 4; idx < 64 * FF; idx += 256 * 4) {
            int r = idx >> 7, c = idx & 127;
            *(float4*)&P_s[r][c] = *(const float4*)&g_P[(jt + r) * FF + c];
        }
        // S tile: 512 elems
        #pragma unroll
        for (int idx = t; idx < 8 * 64; idx += 256) {
            int r = idx >> 6, c = idx & 63;
            S_s[r][c] = g_S[(i0 + r) * NN + jt + c];
        }
        __syncthreads();

        #pragma unroll 4
        for (int jj = 0; jj < 64; jj += 4) {
            float4 sv = *(const float4*)&S_s[ti][jj];      // warp-uniform
            float4 p0 = *(const float4*)&P_s[jj + 0][tg];
            float4 p1 = *(const float4*)&P_s[jj + 1][tg];
            float4 p2 = *(const float4*)&P_s[jj + 2][tg];
            float4 p3 = *(const float4*)&P_s[jj + 3][tg];
            acc0 += sv.x * p0.x; acc1 += sv.x * p0.y; acc2 += sv.x * p0.z; acc3 += sv.x * p0.w;
            acc0 += sv.y * p1.x; acc1 += sv.y * p1.y; acc2 += sv.y * p1.z; acc3 += sv.y * p1.w;
            acc0 += sv.z * p2.x; acc1 += sv.z * p2.y; acc2 += sv.z * p2.z; acc3 += sv.z * p2.w;
            acc0 += sv.w * p3.x; acc1 += sv.w * p3.y; acc2 += sv.w * p3.z; acc3 += sv.w * p3.w;
        }
    }

    const int i = i0 + ti;
    float4 bv = *(const float4*)&bias[tg];
    float4 res;
    res.x = acc0 + bv.x; res.y = acc1 + bv.y;
    res.z = acc2 + bv.z; res.w = acc3 + bv.w;
    *(float4*)&out[i * FF + tg] = res;
}

// ---------------------------------------------------------------------------
extern "C" void kernel_launch(void* const* d_in, const int* in_sizes, int n_in,
                              void* d_out, int out_size)
{
    const float* input   = (const float*)d_in[0];   // [1024,128]
    const float* adj     = (const float*)d_in[1];   // [1024,1024]
    // d_in[2] = feat_adj : unused by the reference
    const float* weight  = (const float*)d_in[3];   // [128,128]
    const float* bias    = (const float*)d_in[4];   // [128]
    const float* w1      = (const float*)d_in[5];   // [128,256]
    const float* b1      = (const float*)d_in[6];   // [128]
    float* out = (float*)d_out;                     // [1024,128]

    prep_kernel<<<dim3(64, 3), 128>>>(input, w1, b1, weight);
    gate_kernel<<<dim3(32, 32), 256>>>(adj);
    out_kernel<<<128, 256>>>(bias, out);
}

// round 3
// speedup vs baseline: 2.5633x; 1.5628x over previous
#include <cuda_runtime.h>

#define NN 1024
#define FF 128

// Scratch (allocation-free rule: __device__ globals)
__device__ float g_A2[NN * FF];       // 0.5 * (input @ w1a^T)             [j,f]
__device__ float g_B2[NN * FF];       // 0.5 * (input @ w1b^T + b1)        [i,f]
__device__ float g_P [NN * FF];       // input @ weight                    [j,g]

__device__ __forceinline__ float tanhf_approx(float x) {
    float y; asm("tanh.approx.f32 %0, %1;" : "=f"(y) : "f"(x)); return y;
}

// ---------------------------------------------------------------------------
// Kernel 1: A2, B2, P (+ out := bias init).
// grid (128, 4), block 256, 8 rows per block -> 4096 warps chip-wide.
// Thread = (col = t&127, row-half = t>>7 owning 4 rows). 4 accumulators.
// w1 staged TRANSPOSED in smem (w_s[k][f], pad 133 -> conflict-free both ways).
// ---------------------------------------------------------------------------
__global__ __launch_bounds__(256) void prep_kernel(
        const float* __restrict__ input,
        const float* __restrict__ w1,
        const float* __restrict__ b1,
        const float* __restrict__ weight,
        const float* __restrict__ bias,
        float* __restrict__ out)
{
    const int mat = blockIdx.y;       // 0 = A2, 1 = B2, 2 = P, 3 = out init
    const int t   = threadIdx.x;      // 0..255
    const int col = t & 127;
    const int rh  = t >> 7;           // 0..1 -> rows rh*4 .. rh*4+3
    const int j0  = blockIdx.x * 8;

    if (mat == 3) {                   // out = bias (gate epilogue atomically adds)
        const float bv = bias[col];
        #pragma unroll
        for (int r = 0; r < 4; r++)
            out[(j0 + rh * 4 + r) * FF + col] = bv;
        return;
    }

    __shared__ float in_s[8][FF];     // 4 KB
    __shared__ float w_s[32][133];    // 17 KB, transposed w1 chunk

    for (int idx = t; idx < 8 * FF; idx += 256)
        in_s[idx >> 7][idx & 127] = input[(j0 + (idx >> 7)) * FF + (idx & 127)];

    float acc[4] = {0.f, 0.f, 0.f, 0.f};

    if (mat < 2) {
        const int off = mat ? 128 : 0;
        for (int k0 = 0; k0 < 128; k0 += 32) {
            __syncthreads();
            // coalesced global read (t -> consecutive k), transposed smem write
            for (int idx = t; idx < 128 * 32; idx += 256) {
                int k = idx & 31, f = idx >> 5;
                w_s[k][f] = w1[f * 256 + off + k0 + k];
            }
            __syncthreads();
            #pragma unroll
            for (int k4 = 0; k4 < 8; k4++) {
                const int k = k4 * 4;
                float w0 = w_s[k + 0][col];
                float w1v = w_s[k + 1][col];
                float w2 = w_s[k + 2][col];
                float w3 = w_s[k + 3][col];
                #pragma unroll
                for (int r = 0; r < 4; r++) {
                    float4 iv = *(const float4*)&in_s[rh * 4 + r][k0 + k];
                    acc[r] += iv.x * w0;
                    acc[r] += iv.y * w1v;
                    acc[r] += iv.z * w2;
                    acc[r] += iv.w * w3;
                }
            }
        }
        if (mat == 0) {
            #pragma unroll
            for (int r = 0; r < 4; r++)
                g_A2[(j0 + rh * 4 + r) * FF + col] = 0.5f * acc[r];
        } else {
            const float bb = b1[col];
            #pragma unroll
            for (int r = 0; r < 4; r++)
                g_B2[(j0 + rh * 4 + r) * FF + col] = 0.5f * (acc[r] + bb);
        }
    } else {
        __syncthreads();
        // P[j,g] = sum_k input[j,k] * weight[k,g]; weight reads coalesced, L1-hot
        #pragma unroll 4
        for (int k4 = 0; k4 < 32; k4++) {
            const int k = k4 * 4;
            float w0 = weight[(k + 0) * FF + col];
            float w1v = weight[(k + 1) * FF + col];
            float w2 = weight[(k + 2) * FF + col];
            float w3 = weight[(k + 3) * FF + col];
            #pragma unroll
            for (int r = 0; r < 4; r++) {
                float4 iv = *(const float4*)&in_s[rh * 4 + r][k];
                acc[r] += iv.x * w0;
                acc[r] += iv.y * w1v;
                acc[r] += iv.z * w2;
                acc[r] += iv.w * w3;
            }
        }
        #pragma unroll
        for (int r = 0; r < 4; r++)
            g_P[(j0 + rh * 4 + r) * FF + col] = acc[r];
    }
}

// ---------------------------------------------------------------------------
// Kernel 2 (fused gate + output GEMM):
//   S[i,j] = adj[i,j] * (64 + 0.5 * sum_f tanh(A2[j,f]+B2[i,f]))
//   out[i,g] += sum_j S[i,j] * P[j,g]        (atomicAdd; out pre-set to bias)
// grid (32, 32), block 256. 32x32 (i,j) tile; thread owns 2x2 at stride 16.
// smem region reused: phase 1 = {a_s,b_s}, phase 2 = {P_s,S_s}.
// ---------------------------------------------------------------------------
__global__ __launch_bounds__(256) void gate_kernel(const float* __restrict__ adj,
                                                   float* __restrict__ out)
{
    __shared__ __align__(16) float buf[2 * 32 * 132];   // 33792 B

    float (*a_s)[132] = (float(*)[132])buf;             // A2 rows, j-tile
    float (*b_s)[132] = (float(*)[132])(buf + 32 * 132);// B2 rows, i-tile

    const int t  = threadIdx.x;              // 0..255
    const int i0 = blockIdx.y * 32;
    const int j0 = blockIdx.x * 32;

    for (int idx = t; idx < 32 * FF; idx += 256) {
        int r = idx >> 7, c = idx & 127;
        a_s[r][c] = g_A2[(j0 + r) * FF + c];
        b_s[r][c] = g_B2[(i0 + r) * FF + c];
    }
    __syncthreads();

    const int ti = t >> 4;       // 0..15 -> i rows {ti, ti+16}
    const int tj = t & 15;       // 0..15 -> j rows {tj, tj+16}

    // issue adj loads early; long-scoreboard hides under the tanh loop
    const int ia = i0 + ti, ib = i0 + ti + 16;
    const int ja = j0 + tj, jb = j0 + tj + 16;
    const float adj00 = adj[ia * NN + ja];
    const float adj01 = adj[ia * NN + jb];
    const float adj10 = adj[ib * NN + ja];
    const float adj11 = adj[ib * NN + jb];

    float acc00 = 0.f, acc01 = 0.f, acc10 = 0.f, acc11 = 0.f;

#define TERM(av, bv) tanhf_approx((av) + (bv))
    #pragma unroll 2
    for (int f = 0; f < FF; f += 4) {
        float4 aA = *(const float4*)&a_s[tj     ][f];
        float4 aB = *(const float4*)&a_s[tj + 16][f];
        float4 bA = *(const float4*)&b_s[ti     ][f];
        float4 bB = *(const float4*)&b_s[ti + 16][f];

        acc00 += TERM(aA.x, bA.x); acc00 += TERM(aA.y, bA.y);
        acc00 += TERM(aA.z, bA.z); acc00 += TERM(aA.w, bA.w);

        acc01 += TERM(aB.x, bA.x); acc01 += TERM(aB.y, bA.y);
        acc01 += TERM(aB.z, bA.z); acc01 += TERM(aB.w, bA.w);

        acc10 += TERM(aA.x, bB.x); acc10 += TERM(aA.y, bB.y);
        acc10 += TERM(aA.z, bB.z); acc10 += TERM(aA.w, bB.w);

        acc11 += TERM(aB.x, bB.x); acc11 += TERM(aB.y, bB.y);
        acc11 += TERM(aB.z, bB.z); acc11 += TERM(aB.w, bB.w);
    }
#undef TERM

    const float s00 = adj00 * (64.0f + 0.5f * acc00);
    const float s01 = adj01 * (64.0f + 0.5f * acc01);
    const float s10 = adj10 * (64.0f + 0.5f * acc10);
    const float s11 = adj11 * (64.0f + 0.5f * acc11);

    __syncthreads();   // all a_s/b_s reads done -> smem reuse

    float (*P_s)[128] = (float(*)[128])buf;              // 16 KB
    float (*S_s)[36]  = (float(*)[36])(buf + 32 * 128);  // 4.6 KB, 16B-aligned rows

    for (int idx = t * 4; idx < 32 * FF; idx += 256 * 4)
        *(float4*)&P_s[idx >> 7][idx & 127] =
            *(const float4*)&g_P[(j0 + (idx >> 7)) * FF + (idx & 127)];

    S_s[ti     ][tj     ] = s00;
    S_s[ti     ][tj + 16] = s01;
    S_s[ti + 16][tj     ] = s10;
    S_s[ti + 16][tj + 16] = s11;
    __syncthreads();

    // Epilogue: out_tile[32,128] += S_s[32,32] @ P_s[32,128]
    const int g    = t & 127;
    const int half = t >> 7;            // 0..1 -> i rows half*16 .. +15

    float oacc[16];
    #pragma unroll
    for (int r = 0; r < 16; r++) oacc[r] = 0.f;

    #pragma unroll
    for (int j4 = 0; j4 < 8; j4++) {
        const int j = j4 * 4;
        float p0 = P_s[j + 0][g];
        float p1 = P_s[j + 1][g];
        float p2 = P_s[j + 2][g];
        float p3 = P_s[j + 3][g];
        #pragma unroll
        for (int r = 0; r < 16; r++) {
            float4 sv = *(const float4*)&S_s[half * 16 + r][j];   // broadcast
            oacc[r] += sv.x * p0;
            oacc[r] += sv.y * p1;
            oacc[r] += sv.z * p2;
            oacc[r] += sv.w * p3;
        }
    }

    #pragma unroll
    for (int r = 0; r < 16; r++)
        atomicAdd(&out[(i0 + half * 16 + r) * FF + g], oacc[r]);
}

// ---------------------------------------------------------------------------
extern "C" void kernel_launch(void* const* d_in, const int* in_sizes, int n_in,
                              void* d_out, int out_size)
{
    const float* input   = (const float*)d_in[0];   // [1024,128]
    const float* adj     = (const float*)d_in[1];   // [1024,1024]
    // d_in[2] = feat_adj : unused by the reference
    const float* weight  = (const float*)d_in[3];   // [128,128]
    const float* bias    = (const float*)d_in[4];   // [128]
    const float* w1      = (const float*)d_in[5];   // [128,256]
    const float* b1      = (const float*)d_in[6];   // [128]
    float* out = (float*)d_out;                     // [1024,128]

    prep_kernel<<<dim3(128, 4), 256>>>(input, w1, b1, weight, bias, out);
    gate_kernel<<<dim3(32, 32), 256>>>(adj, out);
}

// round 4
// speedup vs baseline: 2.7535x; 1.0742x over previous
#include <cuda_runtime.h>
#include <cuda_bf16.h>

#define NN 1024
#define FF 128

// Scratch (allocation-free rule: __device__ globals)
__device__ __nv_bfloat16 g_A2h[NN * FF];  // bf16: 0.5 * (input @ w1a^T)        [j,f]
__device__ __nv_bfloat16 g_B2h[NN * FF];  // bf16: 0.5 * (input @ w1b^T + b1)   [i,f]
__device__ float         g_P  [NN * FF];  // input @ weight                     [j,g]
__device__ float         g_w1t[256 * FF]; // w1 transposed: w1t[k][f] = w1[f][k]

__device__ __forceinline__ float tanhf_approx(float x) {
    float y; asm("tanh.approx.f32 %0, %1;" : "=f"(y) : "f"(x)); return y;
}

// ---------------------------------------------------------------------------
// Kernel 0: transpose w1 [128,256] -> g_w1t [256,128]. grid (8,4), block 256.
// ---------------------------------------------------------------------------
__global__ void transpose_w1_kernel(const float* __restrict__ w1)
{
    __shared__ float tile[32][33];
    const int k0 = blockIdx.x * 32, f0 = blockIdx.y * 32;
    const int c = threadIdx.x & 31, r8 = threadIdx.x >> 5;
    #pragma unroll
    for (int r = r8; r < 32; r += 8)
        tile[r][c] = w1[(f0 + r) * 256 + k0 + c];
    __syncthreads();
    #pragma unroll
    for (int r = r8; r < 32; r += 8)
        g_w1t[(k0 + r) * FF + f0 + c] = tile[c][r];
}

// ---------------------------------------------------------------------------
// Kernel 1: A2 (bf16), B2 (bf16), P (f32), out := bias.
// grid (128, 4), block 256, 8 rows/block. All GEMM paths identical, sync-free
// coalesced K-loops over [k][f]-layout weights (g_w1t halves / weight).
// ---------------------------------------------------------------------------
__global__ __launch_bounds__(256) void prep_kernel(
        const float* __restrict__ input,
        const float* __restrict__ b1,
        const float* __restrict__ weight,
        const float* __restrict__ bias,
        float* __restrict__ out)
{
    const int mat = blockIdx.y;       // 0 = A2, 1 = B2, 2 = P, 3 = out init
    const int t   = threadIdx.x;
    const int col = t & 127;
    const int rh  = t >> 7;           // 0..1 -> rows rh*4 .. rh*4+3
    const int j0  = blockIdx.x * 8;

    if (mat == 3) {                   // out = bias (gate epilogue atomically adds)
        const float bv = bias[col];
        #pragma unroll
        for (int r = 0; r < 4; r++)
            out[(j0 + rh * 4 + r) * FF + col] = bv;
        return;
    }

    __shared__ float in_s[8][FF];
    for (int idx = t; idx < 8 * FF; idx += 256)
        in_s[idx >> 7][idx & 127] = input[(j0 + (idx >> 7)) * FF + (idx & 127)];
    __syncthreads();

    const float* __restrict__ wbase =
        (mat == 0) ? g_w1t : (mat == 1) ? (g_w1t + 128 * FF) : weight;

    float acc[4] = {0.f, 0.f, 0.f, 0.f};
    #pragma unroll 4
    for (int k4 = 0; k4 < 32; k4++) {
        const int k = k4 * 4;
        float w0 = wbase[(k + 0) * FF + col];
        float w1v = wbase[(k + 1) * FF + col];
        float w2 = wbase[(k + 2) * FF + col];
        float w3 = wbase[(k + 3) * FF + col];
        #pragma unroll
        for (int r = 0; r < 4; r++) {
            float4 iv = *(const float4*)&in_s[rh * 4 + r][k];
            acc[r] += iv.x * w0;
            acc[r] += iv.y * w1v;
            acc[r] += iv.z * w2;
            acc[r] += iv.w * w3;
        }
    }

    if (mat == 0) {
        #pragma unroll
        for (int r = 0; r < 4; r++)
            g_A2h[(j0 + rh * 4 + r) * FF + col] = __float2bfloat16(0.5f * acc[r]);
    } else if (mat == 1) {
        const float bb = b1[col];
        #pragma unroll
        for (int r = 0; r < 4; r++)
            g_B2h[(j0 + rh * 4 + r) * FF + col] = __float2bfloat16(0.5f * (acc[r] + bb));
    } else {
        #pragma unroll
        for (int r = 0; r < 4; r++)
            g_P[(j0 + rh * 4 + r) * FF + col] = acc[r];
    }
}

// ---------------------------------------------------------------------------
// Kernel 2 (fused gate + output GEMM), bf16x2 gate inputs:
//   S[i,j] = adj[i,j] * (64 + 0.5 * sum_f tanh(A2[j,f]+B2[i,f]))
//   out[i,g] += sum_j S[i,j] * P[j,g]     (atomicAdd; out pre-set to bias)
// grid (32, 32), block 256, <=40 regs for 6 blocks/SM (75% occ).
// Phase-1 smem = packed bf16x2 tiles (16.9 KB); phase-2 reuses for P_s/S_s.
// ---------------------------------------------------------------------------
__global__ __launch_bounds__(256, 6) void gate_kernel(const float* __restrict__ adj,
                                                      float* __restrict__ out)
{
    // union buffer: phase1 = a_s[32][66] + b_s[32][66] (uint = bf16x2) = 16896 B
    //               phase2 = P_s[32][128] f32 (16 KB) + S_s[32][36] (4.6 KB)
    __shared__ __align__(16) float buf[32 * 128 + 32 * 36];

    unsigned* a_s = (unsigned*)buf;              // [32][66]
    unsigned* b_s = (unsigned*)buf + 32 * 66;    // [32][66]

    const int t  = threadIdx.x;              // 0..255
    const int i0 = blockIdx.y * 32;
    const int j0 = blockIdx.x * 32;

    const unsigned* __restrict__ uA = (const unsigned*)g_A2h;
    const unsigned* __restrict__ uB = (const unsigned*)g_B2h;
    for (int idx = t; idx < 32 * 64; idx += 256) {
        int r = idx >> 6, c = idx & 63;
        a_s[r * 66 + c] = uA[(j0 + r) * 64 + c];
        b_s[r * 66 + c] = uB[(i0 + r) * 64 + c];
    }
    __syncthreads();

    const int ti = t >> 4;       // 0..15 -> i rows {ti, ti+16}
    const int tj = t & 15;       // 0..15 -> j rows {tj, tj+16}

    // issue adj loads early; long-scoreboard hides under the tanh loop
    const int ia = i0 + ti, ib = i0 + ti + 16;
    const int ja = j0 + tj, jb = j0 + tj + 16;
    const float adj00 = adj[ia * NN + ja];
    const float adj01 = adj[ia * NN + jb];
    const float adj10 = adj[ib * NN + ja];
    const float adj11 = adj[ib * NN + jb];

    float acc00 = 0.f, acc01 = 0.f, acc10 = 0.f, acc11 = 0.f;

    const unsigned* aA_p = a_s + tj * 66;
    const unsigned* aB_p = a_s + (tj + 16) * 66;
    const unsigned* bA_p = b_s + ti * 66;
    const unsigned* bB_p = b_s + (ti + 16) * 66;

    // per pair: HADD2(bf16) on fma pipe, unpack via SHF/LOP3 on alu pipe,
    // 2x tanh on MUFU, 2x FADD accumulate. MUFU port is the intended limiter.
#define GATE_PAIR(acc, ua, ub)                                                 \
    {                                                                          \
        __nv_bfloat162 _s = __hadd2(*(const __nv_bfloat162*)&(ua),             \
                                    *(const __nv_bfloat162*)&(ub));            \
        unsigned _u = *(unsigned*)&_s;                                         \
        float _lo = __uint_as_float(_u << 16);                                 \
        float _hi = __uint_as_float(_u & 0xFFFF0000u);                         \
        acc += tanhf_approx(_lo);                                              \
        acc += tanhf_approx(_hi);                                              \
    }

    #pragma unroll 4
    for (int f2 = 0; f2 < 64; f2++) {
        unsigned uaA = aA_p[f2];
        unsigned uaB = aB_p[f2];
        unsigned ubA = bA_p[f2];
        unsigned ubB = bB_p[f2];
        GATE_PAIR(acc00, uaA, ubA)
        GATE_PAIR(acc01, uaB, ubA)
        GATE_PAIR(acc10, uaA, ubB)
        GATE_PAIR(acc11, uaB, ubB)
    }
#undef GATE_PAIR

    const float s00 = adj00 * (64.0f + 0.5f * acc00);
    const float s01 = adj01 * (64.0f + 0.5f * acc01);
    const float s10 = adj10 * (64.0f + 0.5f * acc10);
    const float s11 = adj11 * (64.0f + 0.5f * acc11);

    __syncthreads();   // all a_s/b_s reads done -> smem reuse

    float (*P_s)[128] = (float(*)[128])buf;              // 16 KB
    float (*S_s)[36]  = (float(*)[36])(buf + 32 * 128);  // 4.6 KB

    for (int idx = t * 4; idx < 32 * FF; idx += 256 * 4)
        *(float4*)&P_s[idx >> 7][idx & 127] =
            *(const float4*)&g_P[(j0 + (idx >> 7)) * FF + (idx & 127)];

    S_s[ti     ][tj     ] = s00;
    S_s[ti     ][tj + 16] = s01;
    S_s[ti + 16][tj     ] = s10;
    S_s[ti + 16][tj + 16] = s11;
    __syncthreads();

    // Epilogue: out_tile[32,128] += S_s[32,32] @ P_s[32,128]
    const int g    = t & 127;
    const int half = t >> 7;            // 0..1 -> i rows half*16 .. +15

    float oacc[16];
    #pragma unroll
    for (int r = 0; r < 16; r++) oacc[r] = 0.f;

    #pragma unroll
    for (int j4 = 0; j4 < 8; j4++) {
        const int j = j4 * 4;
        float p0 = P_s[j + 0][g];
        float p1 = P_s[j + 1][g];
        float p2 = P_s[j + 2][g];
        float p3 = P_s[j + 3][g];
        #pragma unroll
        for (int r = 0; r < 16; r++) {
            float4 sv = *(const float4*)&S_s[half * 16 + r][j];   // broadcast
            oacc[r] += sv.x * p0;
            oacc[r] += sv.y * p1;
            oacc[r] += sv.z * p2;
            oacc[r] += sv.w * p3;
        }
    }

    #pragma unroll
    for (int r = 0; r < 16; r++)
        atomicAdd(&out[(i0 + half * 16 + r) * FF + g], oacc[r]);
}

// ---------------------------------------------------------------------------
extern "C" void kernel_launch(void* const* d_in, const int* in_sizes, int n_in,
                              void* d_out, int out_size)
{
    const float* input   = (const float*)d_in[0];   // [1024,128]
    const float* adj     = (const float*)d_in[1];   // [1024,1024]
    // d_in[2] = feat_adj : unused by the reference
    const float* weight  = (const float*)d_in[3];   // [128,128]
    const float* bias    = (const float*)d_in[4];   // [128]
    const float* w1      = (const float*)d_in[5];   // [128,256]
    const float* b1      = (const float*)d_in[6];   // [128]
    float* out = (float*)d_out;                     // [1024,128]

    transpose_w1_kernel<<<dim3(8, 4), 256>>>(w1);
    prep_kernel<<<dim3(128, 4), 256>>>(input, b1, weight, bias, out);
    gate_kernel<<<dim3(32, 32), 256>>>(adj, out);
}